// round 2
// baseline (speedup 1.0000x reference)
#include <cuda_runtime.h>

#define B    4
#define CIN  3
#define COUT 16
#define H    256
#define W    256
#define K    5
#define PAD  2

// Intermediate (dilated) buffer: 4*16*256*256 floats = 16 MB, static device scratch.
__device__ float g_mid[B * COUT * H * W];

// ---------------------------------------------------------------------------
// Dilation: out_d[b,o,i,j] = sum_c max_{di,dj}( x[b,c,clamp(i+di-2),clamp(j+dj-2)] + w_d[o,c,di,dj] )
// Block: 32x8 threads, tile 32 cols x 16 rows, each thread computes 2 rows x 1 col
// for ALL 16 output channels (x window reused across o via registers).
// ---------------------------------------------------------------------------
#define DT_W 32
#define DT_H 16

__global__ __launch_bounds__(256) void dilate_kernel(const float* __restrict__ x,
                                                     const float* __restrict__ wd) {
    __shared__ float xs[CIN][DT_H + 4][DT_W + 4];   // x tile with halo 2
    __shared__ float ws[COUT * CIN * K * K];        // 1200 weights

    const int b      = blockIdx.z;
    const int tile_y = blockIdx.y * DT_H;
    const int tile_x = blockIdx.x * DT_W;
    const int tid    = threadIdx.y * 32 + threadIdx.x;

    // Load all dilation weights (contiguous layout matches w_d)
    for (int i = tid; i < COUT * CIN * K * K; i += 256) ws[i] = wd[i];

    // Load x tile with edge-clamped halo
    const int XS_N = CIN * (DT_H + 4) * (DT_W + 4);
    for (int i = tid; i < XS_N; i += 256) {
        int c   = i / ((DT_H + 4) * (DT_W + 4));
        int rem = i % ((DT_H + 4) * (DT_W + 4));
        int r   = rem / (DT_W + 4);
        int col = rem % (DT_W + 4);
        int gi = tile_y + r - PAD;   gi = min(max(gi, 0), H - 1);
        int gj = tile_x + col - PAD; gj = min(max(gj, 0), W - 1);
        xs[c][r][col] = x[((b * CIN + c) * H + gi) * W + gj];
    }
    __syncthreads();

    const int tx = threadIdx.x;
    const int ty = threadIdx.y;

    float acc0[COUT], acc1[COUT];
#pragma unroll
    for (int o = 0; o < COUT; o++) { acc0[o] = 0.0f; acc1[o] = 0.0f; }

#pragma unroll
    for (int c = 0; c < CIN; c++) {
        // Cache the (2+4) x 5 register window for this channel
        float xr[6][5];
#pragma unroll
        for (int ii = 0; ii < 6; ii++)
#pragma unroll
            for (int jj = 0; jj < 5; jj++)
                xr[ii][jj] = xs[c][ty * 2 + ii][tx + jj];

#pragma unroll
        for (int o = 0; o < COUT; o++) {
            float m0 = -1e30f, m1 = -1e30f;
#pragma unroll
            for (int di = 0; di < K; di++) {
#pragma unroll
                for (int dj = 0; dj < K; dj++) {
                    float w = ws[(o * CIN + c) * (K * K) + di * K + dj];
                    m0 = fmaxf(m0, xr[di][dj]     + w);
                    m1 = fmaxf(m1, xr[di + 1][dj] + w);
                }
            }
            acc0[o] += m0;
            acc1[o] += m1;
        }
    }

    const int gi0 = tile_y + ty * 2;
    const int gj  = tile_x + tx;
#pragma unroll
    for (int o = 0; o < COUT; o++) {
        g_mid[((b * COUT + o) * H + gi0)     * W + gj] = acc0[o];
        g_mid[((b * COUT + o) * H + gi0 + 1) * W + gj] = acc1[o];
    }
}

// ---------------------------------------------------------------------------
// Erosion: out[b,o,i,j] = min_{di,dj}( y[b,o,clamp(i+di-2),clamp(j+dj-2)] - w_e[o,di,dj] )
// Each (b,o) plane independent. Block 32x8, tile 32x32, 4 rows per thread.
// ---------------------------------------------------------------------------
#define ET 32

__global__ __launch_bounds__(256) void erode_kernel(const float* __restrict__ we_g,
                                                    float* __restrict__ out) {
    __shared__ float ys[ET + 4][ET + 4];
    __shared__ float we[K * K];

    const int bo     = blockIdx.z;               // b*COUT + o
    const int o      = bo % COUT;
    const int tile_y = blockIdx.y * ET;
    const int tile_x = blockIdx.x * ET;
    const int tid    = threadIdx.y * 32 + threadIdx.x;

    if (tid < K * K) we[tid] = we_g[o * K * K + tid];

    const float* y = g_mid + (size_t)bo * H * W;
    for (int i = tid; i < (ET + 4) * (ET + 4); i += 256) {
        int r   = i / (ET + 4);
        int col = i % (ET + 4);
        int gi = min(max(tile_y + r - PAD, 0), H - 1);
        int gj = min(max(tile_x + col - PAD, 0), W - 1);
        ys[r][col] = y[gi * W + gj];
    }
    __syncthreads();

    const int tx = threadIdx.x;
    const int ty = threadIdx.y;

    float yr[8][5];
#pragma unroll
    for (int ii = 0; ii < 8; ii++)
#pragma unroll
        for (int jj = 0; jj < 5; jj++)
            yr[ii][jj] = ys[ty * 4 + ii][tx + jj];

    float m[4];
#pragma unroll
    for (int p = 0; p < 4; p++) m[p] = 1e30f;

#pragma unroll
    for (int di = 0; di < K; di++) {
#pragma unroll
        for (int dj = 0; dj < K; dj++) {
            float w = we[di * K + dj];
#pragma unroll
            for (int p = 0; p < 4; p++)
                m[p] = fminf(m[p], yr[p + di][dj] - w);
        }
    }

    const int gj = tile_x + tx;
#pragma unroll
    for (int p = 0; p < 4; p++)
        out[((size_t)bo * H + tile_y + ty * 4 + p) * W + gj] = m[p];
}

// ---------------------------------------------------------------------------
extern "C" void kernel_launch(void* const* d_in, const int* in_sizes, int n_in,
                              void* d_out, int out_size) {
    const float* x  = (const float*)d_in[0];
    const float* wd = (const float*)d_in[1];
    const float* we = (const float*)d_in[2];
    float*       out = (float*)d_out;

    dim3 bD(32, 8);
    dim3 gD(W / DT_W, H / DT_H, B);        // 8 x 16 x 4
    dilate_kernel<<<gD, bD>>>(x, wd);

    dim3 bE(32, 8);
    dim3 gE(W / ET, H / ET, B * COUT);     // 8 x 8 x 64
    erode_kernel<<<gE, bE>>>(we, out);
}